// round 17
// baseline (speedup 1.0000x reference)
#include <cuda_runtime.h>
#include <cuda_bf16.h>
#include <math.h>
#include <stdint.h>

#define BHN   16
#define LEN   2048
#define DIM   64
#define MRP   1024
#define QT    16
#define TRI   136
#define OUT_ELEMS ((size_t)BHN*LEN*DIM)

typedef unsigned long long u64;

// scratch
__device__ float    g_R[(size_t)BHN * LEN * MRP];        // rel logits
__device__ uint32_t g_QH[(size_t)BHN * LEN * (DIM/2)];   // split Q hi (bf16x2)
__device__ uint32_t g_QL[(size_t)BHN * LEN * (DIM/2)];
__device__ uint32_t g_KH[(size_t)BHN * LEN * (DIM/2)];
__device__ uint32_t g_KL[(size_t)BHN * LEN * (DIM/2)];
__device__ uint32_t g_EH[(size_t)MRP * (DIM/2)];         // split embed
__device__ uint32_t g_EL[(size_t)MRP * (DIM/2)];
__device__ uint32_t g_VH[(size_t)BHN * DIM * (LEN/2)];   // split V^T [bh][d][j]
__device__ uint32_t g_VL[(size_t)BHN * DIM * (LEN/2)];

// ---------------- split fp32 -> (bf16 hi, bf16 lo) packed pairs ------------
__device__ __forceinline__ void split_pair(float x, float y,
                                           uint32_t &h, uint32_t &l) {
    __nv_bfloat16 hx = __float2bfloat16_rn(x), hy = __float2bfloat16_rn(y);
    float rx = x - __bfloat162float(hx), ry = y - __bfloat162float(hy);
    __nv_bfloat16 lx = __float2bfloat16_rn(rx), ly = __float2bfloat16_rn(ry);
    h = (uint32_t)__bfloat16_as_ushort(hx) | ((uint32_t)__bfloat16_as_ushort(hy) << 16);
    l = (uint32_t)__bfloat16_as_ushort(lx) | ((uint32_t)__bfloat16_as_ushort(ly) << 16);
}

// mma.sync m16n8k16 row.col f32.bf16.bf16.f32 (portable; no 'a'-target)
__device__ __forceinline__ void mma16816(float d[4], uint32_t a0, uint32_t a1,
                                         uint32_t a2, uint32_t a3,
                                         uint32_t b0, uint32_t b1) {
    asm volatile(
        "mma.sync.aligned.m16n8k16.row.col.f32.bf16.bf16.f32 "
        "{%0,%1,%2,%3}, {%4,%5,%6,%7}, {%8,%9}, {%0,%1,%2,%3};"
        : "+f"(d[0]), "+f"(d[1]), "+f"(d[2]), "+f"(d[3])
        : "r"(a0), "r"(a1), "r"(a2), "r"(a3), "r"(b0), "r"(b1));
}

__device__ __forceinline__ void tri_map(int t, int &ti, int &tj) {
    int i = (int)((sqrtf(8.0f * (float)t + 1.0f) - 1.0f) * 0.5f);
    while ((i + 1) * (i + 2) / 2 <= t) i++;
    while (i * (i + 1) / 2 > t) i--;
    ti = i; tj = t - i * (i + 1) / 2;
}

// smem strides (bf16 elems); frag LDS.32 conflict-free (bank = 4g+t distinct)
#define STQ 72
#define STP 136

// half-tile body smem (A 128 rows, B 64 rows, hi+lo each)
#define HB_AH 0
#define HB_AL (128*STQ)
#define HB_BH (2*128*STQ)
#define HB_BL (2*128*STQ + 64*STQ)
#define HB_SMEM ((2*128 + 2*64)*STQ*2)   // 55296 bytes

#define PV_WH 0
#define PV_WL (128*STP)
#define PV_VH (2*128*STP)
#define PV_VL (2*128*STP + 64*STP)
#define PV_SMEM ((2*128*STP + 2*64*STP)*2)  // 104448 bytes

// ---------------- zero the attention-output region -------------------------
__global__ void k_zero(float* __restrict__ O) {
    size_t i = ((size_t)blockIdx.x * 256 + threadIdx.x) * 4;
    *(float4*)(O + i) = make_float4(0.f, 0.f, 0.f, 0.f);
}

// ---------------- pre-split a row-major [rows][64] fp32 tensor -------------
__global__ void __launch_bounds__(256) k_presplit(const float* __restrict__ src,
                                                  uint32_t* __restrict__ dH,
                                                  uint32_t* __restrict__ dL) {
    size_t base = ((size_t)blockIdx.y * gridDim.x + blockIdx.x) * (128 * DIM);
    const float2* s = (const float2*)(src + base);
    uint32_t* h = dH + base / 2;
    uint32_t* l = dL + base / 2;
    #pragma unroll
    for (int it = 0; it < 16; it++) {
        int i = threadIdx.x + it * 256;      // 0..4095 float2
        float2 v = s[i];
        uint32_t hh, ll;
        split_pair(v.x, v.y, hh, ll);
        h[i] = hh; l[i] = ll;
    }
}

// ---------------- V pre-split + transpose: [bh][j][d] -> [bh][d][j] --------
__global__ void __launch_bounds__(256) k_vsplit(const float* __restrict__ V) {
    __shared__ float tr[64][33];
    const int jc = blockIdx.x;           // 32-j chunk
    const int bh = blockIdx.y;
    const int tid = threadIdx.x;
    const float* Vb = V + ((size_t)bh * LEN + jc * 32) * DIM;
    #pragma unroll
    for (int rep = 0; rep < 2; rep++) {
        int f4 = tid + rep * 256;
        int jr = f4 >> 4;
        int d4 = (f4 & 15) * 4;
        float4 v = *(const float4*)(Vb + (size_t)jr * DIM + d4);
        tr[d4+0][jr] = v.x; tr[d4+1][jr] = v.y;
        tr[d4+2][jr] = v.z; tr[d4+3][jr] = v.w;
    }
    __syncthreads();
    #pragma unroll
    for (int rep = 0; rep < 4; rep++) {
        int oi = tid + rep * 256;
        int d = oi >> 4, j2 = oi & 15;
        uint32_t h, l;
        split_pair(tr[d][j2*2], tr[d][j2*2+1], h, l);
        size_t gi = ((size_t)bh * DIM + d) * (LEN/2) + jc * 16 + j2;
        g_VH[gi] = h; g_VL[gi] = l;
    }
}

// ---------------------------------------------------------------------------
// 128x64 NT half-tile body: A[128x64] @ B[64x64]^T, split bf16, 3-product.
// acc[2][4][4] (32 regs) -> ~80 total regs -> 3 CTAs/SM.
// Warp grid 4x2: warp tile 32 rows x 32 cols.
// ---------------------------------------------------------------------------
__device__ __forceinline__ void half_body(const uint32_t* __restrict__ AHg,
                                          const uint32_t* __restrict__ ALg,
                                          const uint32_t* __restrict__ BHg,
                                          const uint32_t* __restrict__ BLg,
                                          uint16_t* sm, float acc[2][4][4]) {
    const int tid = threadIdx.x;
    uint32_t* AH = (uint32_t*)(sm + HB_AH);
    uint32_t* AL = (uint32_t*)(sm + HB_AL);
    uint32_t* BH = (uint32_t*)(sm + HB_BH);
    uint32_t* BL = (uint32_t*)(sm + HB_BL);
    #pragma unroll
    for (int it = 0; it < 4; it++) {         // A: 128 rows x 8 uint4
        int idx = tid + it * 256;
        int row = idx >> 3;
        int grp = idx & 7;
        int so = row * 9 + grp;
        ((uint4*)AH)[so] = *((const uint4*)(AHg + (size_t)row * 32) + grp);
        ((uint4*)AL)[so] = *((const uint4*)(ALg + (size_t)row * 32) + grp);
    }
    #pragma unroll
    for (int it = 0; it < 2; it++) {         // B: 64 rows x 8 uint4
        int idx = tid + it * 256;
        int row = idx >> 3;
        int grp = idx & 7;
        int so = row * 9 + grp;
        ((uint4*)BH)[so] = *((const uint4*)(BHg + (size_t)row * 32) + grp);
        ((uint4*)BL)[so] = *((const uint4*)(BLg + (size_t)row * 32) + grp);
    }
    __syncthreads();

    const int w = tid >> 5, lane = tid & 31;
    const int wr = w >> 1, wc = w & 1;
    const int g = lane >> 2, t = lane & 3;
    #pragma unroll
    for (int ks = 0; ks < 4; ks++) {
        const int k0 = ks * 16 + 2 * t;
        uint32_t ah[2][4], al[2][4];
        #pragma unroll
        for (int mi = 0; mi < 2; mi++) {
            int r = wr * 32 + mi * 16 + g;
            int o0 = (r * STQ + k0) >> 1, o1 = ((r + 8) * STQ + k0) >> 1;
            ah[mi][0] = AH[o0];     ah[mi][1] = AH[o1];
            ah[mi][2] = AH[o0 + 4]; ah[mi][3] = AH[o1 + 4];
            al[mi][0] = AL[o0];     al[mi][1] = AL[o1];
            al[mi][2] = AL[o0 + 4]; al[mi][3] = AL[o1 + 4];
        }
        #pragma unroll
        for (int ni = 0; ni < 4; ni++) {
            int n = wc * 32 + ni * 8 + g;
            int ob = (n * STQ + k0) >> 1;
            uint32_t bh0 = BH[ob], bh1 = BH[ob + 4];
            uint32_t bl0 = BL[ob], bl1 = BL[ob + 4];
            #pragma unroll
            for (int mi = 0; mi < 2; mi++) {
                mma16816(acc[mi][ni], ah[mi][0], ah[mi][1], ah[mi][2], ah[mi][3], bh0, bh1);
                mma16816(acc[mi][ni], ah[mi][0], ah[mi][1], ah[mi][2], ah[mi][3], bl0, bl1);
                mma16816(acc[mi][ni], al[mi][0], al[mi][1], al[mi][2], al[mi][3], bh0, bh1);
            }
        }
    }
}

// ---------------- R = Q @ embed^T (64-col blocks, pruned) ------------------
__global__ void __launch_bounds__(256) k_relgemm(int dummy) {
    const int rt = blockIdx.x, cb = blockIdx.y, bh = blockIdx.z;
    if (rt + (cb >> 1) <= 6) return;     // R[q,e] read only where e >= 1023-q
    extern __shared__ uint16_t smq[];
    float acc[2][4][4];
    #pragma unroll
    for (int a = 0; a < 2; a++)
        #pragma unroll
        for (int b = 0; b < 4; b++)
            #pragma unroll
            for (int c = 0; c < 4; c++) acc[a][b][c] = 0.f;
    const size_t qb = ((size_t)bh * LEN + rt * 128) * 32;
    const size_t eb = (size_t)(cb * 64) * 32;
    half_body(g_QH + qb, g_QL + qb, g_EH + eb, g_EL + eb, smq, acc);

    const int tid = threadIdx.x, w = tid >> 5, lane = tid & 31;
    const int wr = w >> 1, wc = w & 1, g = lane >> 2, t = lane & 3;
    #pragma unroll
    for (int mi = 0; mi < 2; mi++) {
        int q0 = rt * 128 + wr * 32 + mi * 16 + g;
        float* R0 = g_R + ((size_t)bh * LEN + q0) * MRP + cb * 64;
        float* R1 = R0 + 8 * MRP;
        #pragma unroll
        for (int ni = 0; ni < 4; ni++) {
            int c = wc * 32 + ni * 8 + 2 * t;
            *(float2*)(R0 + c) = make_float2(acc[mi][ni][0], acc[mi][ni][1]);
            *(float2*)(R1 + c) = make_float2(acc[mi][ni][2], acc[mi][ni][3]);
        }
    }
}

// ---------------- S = Q @ K^T + rel (half tiles: 128 x 64) -----------------
__global__ void __launch_bounds__(256) k_qk(float* __restrict__ Wt) {
    extern __shared__ uint16_t smq[];
    const int bx = blockIdx.x;
    int ti, tj; tri_map(bx >> 1, ti, tj);
    const int half = bx & 1;
    const int bh = blockIdx.y;
    float acc[2][4][4];
    #pragma unroll
    for (int a = 0; a < 2; a++)
        #pragma unroll
        for (int b = 0; b < 4; b++)
            #pragma unroll
            for (int c = 0; c < 4; c++) acc[a][b][c] = 0.f;
    const size_t qb = ((size_t)bh * LEN + ti * 128) * 32;
    const size_t kb = ((size_t)bh * LEN + tj * 128 + half * 64) * 32;
    half_body(g_QH + qb, g_QL + qb, g_KH + kb, g_KL + kb, smq, acc);

    const int tid = threadIdx.x, w = tid >> 5, lane = tid & 31;
    const int wr = w >> 1, wc = w & 1, g = lane >> 2, t = lane & 3;
    const int jbase = tj * 128 + half * 64;
    #pragma unroll
    for (int mi = 0; mi < 2; mi++) {
        #pragma unroll
        for (int rh = 0; rh < 2; rh++) {
            int q0 = ti * 128 + wr * 32 + mi * 16 + g + rh * 8;
            const float* Rrow = g_R + ((size_t)bh * LEN + q0) * MRP;
            float* Wrow = Wt + ((size_t)bh * LEN + q0) * LEN + jbase;
            #pragma unroll
            for (int ni = 0; ni < 4; ni++) {
                int c = wc * 32 + ni * 8 + 2 * t;
                int j = jbase + c;
                int rp = j - q0 + (MRP - 1);
                float r0 = (rp >= 0 && rp < MRP) ? Rrow[rp] : 0.f;
                int rp1 = rp + 1;
                float r1 = (rp1 >= 0 && rp1 < MRP) ? Rrow[rp1] : 0.f;
                float x0 = acc[mi][ni][2 * rh + 0] + r0;
                float x1 = acc[mi][ni][2 * rh + 1] + r1;
                *(float2*)(Wrow + c) = make_float2(x0, x1);
            }
        }
    }
}

// ---------------- row softmax (proven 67.9us version) ----------------------
__global__ void __launch_bounds__(256) k_softmax(float* __restrict__ Wt) {
    const int q  = blockIdx.x & (LEN - 1);
    const int bh = blockIdx.x >> 11;
    float* Wrow = Wt + ((size_t)bh * LEN + q) * LEN;
    const int tid = threadIdx.x;
    const int ja = tid * 4, jb = 1024 + tid * 4;
    float4 wa = make_float4(-3e38f, -3e38f, -3e38f, -3e38f), wb = wa;
    if (ja <= q) wa = *(const float4*)(Wrow + ja);
    if (jb <= q) wb = *(const float4*)(Wrow + jb);
    float va[4] = {wa.x, wa.y, wa.z, wa.w};
    float vb[4] = {wb.x, wb.y, wb.z, wb.w};

    float m = -3.0e38f;
    #pragma unroll
    for (int c = 0; c < 4; c++) {
        if (ja + c <= q) m = fmaxf(m, va[c]);
        if (jb + c <= q) m = fmaxf(m, vb[c]);
    }
    __shared__ float red[9];
    #pragma unroll
    for (int o = 16; o > 0; o >>= 1) m = fmaxf(m, __shfl_xor_sync(0xffffffffu, m, o));
    if ((tid & 31) == 0) red[tid >> 5] = m;
    __syncthreads();
    if (tid == 0) {
        float x = red[0];
        #pragma unroll
        for (int w = 1; w < 8; w++) x = fmaxf(x, red[w]);
        red[8] = x;
    }
    __syncthreads();
    const float bm = red[8];

    float ea[4], eb[4], s = 0.f;
    #pragma unroll
    for (int c = 0; c < 4; c++) {
        ea[c] = (ja + c <= q) ? __expf(va[c] - bm) : 0.f;
        eb[c] = (jb + c <= q) ? __expf(vb[c] - bm) : 0.f;
        s += ea[c] + eb[c];
    }
    __syncthreads();
    #pragma unroll
    for (int o = 16; o > 0; o >>= 1) s += __shfl_xor_sync(0xffffffffu, s, o);
    if ((tid & 31) == 0) red[tid >> 5] = s;
    __syncthreads();
    if (tid == 0) {
        float x = red[0];
        #pragma unroll
        for (int w = 1; w < 8; w++) x += red[w];
        red[8] = x;
    }
    __syncthreads();
    const float inv = 1.0f / red[8];
    *(float4*)(Wrow + ja) = make_float4(ea[0]*inv, ea[1]*inv, ea[2]*inv, ea[3]*inv);
    *(float4*)(Wrow + jb) = make_float4(eb[0]*inv, eb[1]*inv, eb[2]*inv, eb[3]*inv);
}

// ---------------- O = W @ V (40-chunk balanced split-K) --------------------
// Band ti has ti/4+1 chunks; chunk tiles split evenly. 40 blocks per bh.
__global__ void __launch_bounds__(256, 2) k_pv(const float* __restrict__ Wt,
                                               float* __restrict__ O) {
    extern __shared__ uint16_t smp[];
    int s = blockIdx.x;
    const int bh = blockIdx.y;
    int ti = 0;
    while (s >= ti / 4 + 1) { s -= ti / 4 + 1; ti++; }
    const int nch = ti / 4 + 1, cnt = ti + 1;
    const int qq = cnt / nch, rr = cnt % nch;
    const int tj0 = s * qq + (s < rr ? s : rr);
    const int tj1 = tj0 + qq + (s < rr ? 1 : 0);

    uint32_t* WH = (uint32_t*)(smp + PV_WH);
    uint32_t* WL = (uint32_t*)(smp + PV_WL);
    uint32_t* VH = (uint32_t*)(smp + PV_VH);
    uint32_t* VL = (uint32_t*)(smp + PV_VL);

    const int tid = threadIdx.x, w = tid >> 5, lane = tid & 31;
    const int wr = w >> 1, wc = w & 1, g = lane >> 2, t = lane & 3;

    float acc[2][4][4];
    #pragma unroll
    for (int a = 0; a < 2; a++)
        #pragma unroll
        for (int b = 0; b < 4; b++)
            #pragma unroll
            for (int c = 0; c < 4; c++) acc[a][b][c] = 0.f;

    for (int tj = tj0; tj < tj1; tj++) {
        const float* Wg = Wt + ((size_t)bh * LEN + ti * 128) * LEN + tj * 128;
        __syncthreads();
        #pragma unroll
        for (int it = 0; it < 16; it++) {       // W: 128x128 -> 4096 float4
            int idx = tid + it * 256;
            int row = idx >> 5;
            int c4  = (idx & 31) * 4;
            int so  = (row * STP + c4) >> 1;
            float4 vv = *(const float4*)(Wg + (size_t)row * LEN + c4);
            uint32_t h, l;
            split_pair(vv.x, vv.y, h, l); WH[so] = h;     WL[so] = l;
            split_pair(vv.z, vv.w, h, l); WH[so + 1] = h; WL[so + 1] = l;
        }
        #pragma unroll
        for (int it = 0; it < 4; it++) {        // V: pre-split copy
            int li = tid + it * 256;
            int d = li >> 4, j4 = (li & 15) * 4;
            size_t gi = ((size_t)bh * DIM + d) * (LEN/2) + tj * 64 + j4;
            *(uint4*)&VH[d * 68 + j4] = *(const uint4*)&g_VH[gi];
            *(uint4*)&VL[d * 68 + j4] = *(const uint4*)&g_VL[gi];
        }
        __syncthreads();

        #pragma unroll
        for (int ks = 0; ks < 8; ks++) {
            const int k0 = ks * 16 + 2 * t;
            uint32_t ah[2][4], al[2][4];
            #pragma unroll
            for (int mi = 0; mi < 2; mi++) {
                int r = wr * 32 + mi * 16 + g;
                int o0 = (r * STP + k0) >> 1, o1 = ((r + 8) * STP + k0) >> 1;
                ah[mi][0] = WH[o0];     ah[mi][1] = WH[o1];
                ah[mi][2] = WH[o0 + 4]; ah[mi][3] = WH[o1 + 4];
                al[mi][0] = WL[o0];     al[mi][1] = WL[o1];
                al[mi][2] = WL[o0 + 4]; al[mi][3] = WL[o1 + 4];
            }
            #pragma unroll
            for (int ni = 0; ni < 4; ni++) {
                int n = wc * 32 + ni * 8 + g;
                int ob = (n * STP + k0) >> 1;
                uint32_t bh0 = VH[ob], bh1 = VH[ob + 4];
                uint32_t bl0 = VL[ob], bl1 = VL[ob + 4];
                #pragma unroll
                for (int mi = 0; mi < 2; mi++) {
                    mma16816(acc[mi][ni], ah[mi][0], ah[mi][1], ah[mi][2], ah[mi][3], bh0, bh1);
                    mma16816(acc[mi][ni], ah[mi][0], ah[mi][1], ah[mi][2], ah[mi][3], bl0, bl1);
                    mma16816(acc[mi][ni], al[mi][0], al[mi][1], al[mi][2], al[mi][3], bh0, bh1);
                }
            }
        }
    }

    #pragma unroll
    for (int mi = 0; mi < 2; mi++) {
        #pragma unroll
        for (int rh = 0; rh < 2; rh++) {
            int row = ti * 128 + wr * 32 + mi * 16 + g + rh * 8;
            float* orow = O + ((size_t)bh * LEN + row) * DIM;
            #pragma unroll
            for (int ni = 0; ni < 4; ni++) {
                int c = wc * 32 + ni * 8 + 2 * t;
                atomicAdd(orow + c,     acc[mi][ni][2 * rh + 0]);
                atomicAdd(orow + c + 1, acc[mi][ni][2 * rh + 1]);
            }
        }
    }
}

// ---------------------------------------------------------------------------
extern "C" void kernel_launch(void* const* d_in, const int* in_sizes, int n_in,
                              void* d_out, int out_size) {
    const float* q   = (const float*)d_in[0];
    const float* k   = (const float*)d_in[1];
    const float* v   = (const float*)d_in[2];
    const float* rel = (const float*)d_in[3];

    float* out = (float*)d_out;
    float* Wt  = out + OUT_ELEMS;

    cudaFuncSetAttribute(k_relgemm, cudaFuncAttributeMaxDynamicSharedMemorySize, HB_SMEM);
    cudaFuncSetAttribute(k_qk,      cudaFuncAttributeMaxDynamicSharedMemorySize, HB_SMEM);
    cudaFuncSetAttribute(k_pv,      cudaFuncAttributeMaxDynamicSharedMemorySize, PV_SMEM);

    k_zero<<<(unsigned)(OUT_ELEMS / 1024), 256>>>(out);

    // pre-split all GEMM operands to bf16 hi/lo (one-time)
    uint32_t *qh, *ql, *kh, *kl, *eh, *el;
    cudaGetSymbolAddress((void**)&qh, g_QH);
    cudaGetSymbolAddress((void**)&ql, g_QL);
    cudaGetSymbolAddress((void**)&kh, g_KH);
    cudaGetSymbolAddress((void**)&kl, g_KL);
    cudaGetSymbolAddress((void**)&eh, g_EH);
    cudaGetSymbolAddress((void**)&el, g_EL);
    dim3 gs(QT, BHN);
    k_presplit<<<gs, 256>>>(q, qh, ql);
    k_presplit<<<gs, 256>>>(k, kh, kl);
    dim3 ge(MRP / 128, 1);
    k_presplit<<<ge, 256>>>(rel, eh, el);

    dim3 gv(LEN / 32, BHN);
    k_vsplit<<<gv, 256>>>(v);

    dim3 g0(QT, MRP / 64, BHN);
    k_relgemm<<<g0, 256, HB_SMEM>>>(0);

    dim3 g1(TRI * 2, BHN);
    k_qk<<<g1, 256, HB_SMEM>>>(Wt);

    k_softmax<<<BHN * LEN, 256>>>(Wt);

    dim3 g2(40, BHN);
    k_pv<<<g2, 256, PV_SMEM>>>(Wt, out);
}